// round 9
// baseline (speedup 1.0000x reference)
#include <cuda_runtime.h>
#include <math.h>

#define BN 4
#define CCH 21
#define HH 96
#define WW 96
#define NN (HH*WW)          // 9216
#define NEH (HH*(WW-1))     // 9120
#define NEV ((HH-1)*WW)     // 9120
#define NE  (NEH+NEV)       // 18240
#define NTREE 8             // s = b*2 + t, t=0 low, t=1 high
#define NCHUNK 32
#define CHSZ  16            // 512 / NCHUNK
#define ROOT  (48*WW + 48)  // center root (two-pass filter is root-invariant)

// ---------------- scratch ----------------
__device__ double g_ws[NTREE*NE];
__device__ unsigned long long g_key[NTREE*NE];
__device__ double g_part[BN*NCHUNK*NE];
__device__ int    g_adj[NTREE*NN*4];
__device__ int    g_ord[NTREE*NN];     // node at BFS position
__device__ int    g_pp[NTREE*NN];      // parent BFS position
__device__ int    g_cs[NTREE*NN];      // (childcount<<14)|childstart, BFS-pos indexed
__device__ int    g_loff[NTREE*(NN+4)];
__device__ int    g_nlev[NTREE];
__device__ float  g_w[NTREE*NN];       // weight, BFS-position-indexed
__device__ float  g_prob[BN*CCH*NN];
__device__ float  g_S[BN*(CCH+1)*NN];
__device__ float  g_S2[BN*(CCH+1)*NN];
__device__ double g_acc[2];

__device__ __forceinline__ void edge_nodes(int e, int &a, int &b) {
    if (e < NEH) { int r = e / (WW-1); int c = e - r*(WW-1); a = r*WW + c; b = a + 1; }
    else         { a = e - NEH; b = a + WW; }
}

__device__ __forceinline__ unsigned long long pack_key(double w, int e) {
    unsigned long long kb = (unsigned long long)__double_as_longlong(w);
    return (kb & ~32767ull) | (unsigned long long)e;
}

__device__ __forceinline__ void two_sum(float a, float b, float &s, float &e) {
    s = __fadd_rn(a, b);
    float bp = __fsub_rn(s, a);
    e = __fadd_rn(__fsub_rn(a, __fsub_rn(s, bp)), __fsub_rn(b, bp));
}

// ---------------- kernels ----------------
__global__ void k_sigmoid(const float* __restrict__ preds) {
    int i = blockIdx.x*blockDim.x + threadIdx.x;
    if (i < 2) g_acc[i] = 0.0;
    if (i < BN*CCH*NN) g_prob[i] = 1.0f/(1.0f + expf(-preds[i]));
}

__global__ void k_ew_high(const float* __restrict__ hf) {
    int idx = blockIdx.x*blockDim.x + threadIdx.x;
    if (idx >= BN*NCHUNK*NE) return;
    int b = idx / (NCHUNK*NE);
    int r = idx - b*(NCHUNK*NE);
    int ch = r / NE, e = r - ch*NE;
    int a, bb; edge_nodes(e, a, bb);
    const float* f = hf + b*512*NN + ch*CHSZ*NN;
    float sh = 0.0f, sl = 0.0f;
    #pragma unroll
    for (int c = 0; c < CHSZ; c++) {
        float av = f[c*NN+a], bv = f[c*NN+bb];
        float dh, dl; two_sum(av, -bv, dh, dl);
        float p  = __fmul_rn(dh, dh);
        float pe = __fmaf_rn(dh, dh, -p);
        pe = __fmaf_rn(__fmul_rn(2.0f, dh), dl, pe);
        float t, er; two_sum(sh, p, t, er);
        sl = __fadd_rn(sl, __fadd_rn(er, pe));
        sh = t;
    }
    g_part[(b*NCHUNK + ch)*NE + e] = (double)sh + (double)sl;
}

__global__ void k_ew_red(const float* __restrict__ lf) {
    int idx = blockIdx.x*blockDim.x + threadIdx.x;
    if (idx >= BN*NE) return;
    int b = idx / NE, e = idx - b*NE;
    int a, bb; edge_nodes(e, a, bb);
    const float* f = lf + b*3*NN;
    double accl = 0.0;
    #pragma unroll
    for (int c = 0; c < 3; c++) {
        double d = (double)f[c*NN+a] - (double)f[c*NN+bb];
        accl += d*d;
    }
    g_ws[(b*2)*NE + e] = accl;
    g_key[(b*2)*NE + e] = pack_key(accl, e);
    double acc = 0.0;
    #pragma unroll 8
    for (int ch = 0; ch < NCHUNK; ch++) acc += g_part[(b*NCHUNK + ch)*NE + e];
    g_ws[(b*2+1)*NE + e] = acc;
    g_key[(b*2+1)*NE + e] = pack_key(acc, e);
}

// Parallel Boruvka, one block per tree.
__global__ void __launch_bounds__(1024) k_boruvka() {
    extern __shared__ unsigned long long sh_u[];
    unsigned long long* minw = sh_u;       // NN
    int* parent = (int*)(minw + NN);       // NN
    int* hook   = parent + NN;             // NN
    int* deg    = hook + NN;               // NN
    __shared__ int total, flag;
    int s = blockIdx.x;
    const unsigned long long* key = g_key + s*NE;
    int* adj = g_adj + s*NN*4;
    for (int i = threadIdx.x; i < NN; i += blockDim.x) { parent[i] = i; deg[i] = 0; }
    for (int i = threadIdx.x; i < NN*4; i += blockDim.x) adj[i] = -1;
    if (threadIdx.x == 0) total = 0;
    __syncthreads();
    for (int round = 0; round < 24; round++) {
        for (int i = threadIdx.x; i < NN; i += blockDim.x) {
            minw[i] = 0xFFFFFFFFFFFFFFFFull; hook[i] = -1;
        }
        __syncthreads();
        for (int e = threadIdx.x; e < NE; e += blockDim.x) {
            int a, b; edge_nodes(e, a, b);
            int ra = parent[a], rb = parent[b];
            if (ra != rb) {
                unsigned long long k = key[e];
                if (k < minw[ra]) atomicMin(&minw[ra], k);
                if (k < minw[rb]) atomicMin(&minw[rb], k);
            }
        }
        __syncthreads();
        for (int i = threadIdx.x; i < NN; i += blockDim.x) {
            unsigned long long mk = minw[i];
            if (parent[i] == i && mk != 0xFFFFFFFFFFFFFFFFull) {
                int e = (int)(mk & 32767ull);
                int a, b; edge_nodes(e, a, b);
                int ra = parent[a], rb = parent[b];
                int other = (ra == i) ? rb : ra;
                bool mutual = (minw[other] == mk);
                if (!mutual || i < other) {
                    int da = atomicAdd(&deg[a], 1); adj[a*4+da] = b;
                    int db = atomicAdd(&deg[b], 1); adj[b*4+db] = a;
                    atomicAdd(&total, 1);
                    hook[i] = other;
                }
            }
        }
        __syncthreads();
        for (int i = threadIdx.x; i < NN; i += blockDim.x) {
            int t = hook[i];
            if (t >= 0) parent[i] = t;
        }
        __syncthreads();
        for (;;) {
            if (threadIdx.x == 0) flag = 0;
            __syncthreads();
            for (int i = threadIdx.x; i < NN; i += blockDim.x) {
                int p = parent[i], gp = parent[p];
                if (p != gp) { parent[i] = gp; flag = 1; }
            }
            __syncthreads();
            int f = flag;
            __syncthreads();
            if (!f) break;
        }
        if (total >= NN-1) break;
    }
}

// Single-warp BFS from ROOT. Children written SORTED BY PARENT (ballot prefix),
// so children of a node are contiguous in the next level. Emits ord, pp,
// cspack=(cc<<14)|cs, level offsets; tail computes position-indexed weights.
__global__ void __launch_bounds__(256) k_bfs() {
    extern __shared__ int sh[];
    int* adj_s = sh;            // NN*4
    int* ord   = adj_s + NN*4;  // NN
    int* pp    = ord + NN;      // NN
    int s = blockIdx.x;
    const int* adj = g_adj + s*NN*4;
    int* loff = g_loff + s*(NN+4);
    for (int i = threadIdx.x; i < NN*4; i += blockDim.x) adj_s[i] = adj[i];
    if (threadIdx.x == 0) { ord[0] = ROOT; pp[0] = 0; loff[0] = 0; loff[1] = 1; }
    __syncthreads();
    if (threadIdx.x < 32) {
        int lane = threadIdx.x;
        unsigned lt = (1u << lane) - 1u;
        int cur = 0, curEnd = 1, lvl = 0;
        for (;;) {
            int total = 0;
            for (int q0 = cur; q0 < curEnd; q0 += 32) {
                int q = q0 + lane;
                int nc = 0; int ch[4];
                if (q < curEnd) {
                    int u = ord[q];
                    int pu = (q == 0) ? -1 : ord[pp[q]];
                    #pragma unroll
                    for (int j = 0; j < 4; j++) {
                        int v = adj_s[u*4 + j];
                        if (v >= 0 && v != pu) ch[nc++] = v;
                    }
                }
                unsigned m0 = __ballot_sync(0xffffffffu, nc > 0);
                unsigned m1 = __ballot_sync(0xffffffffu, nc > 1);
                unsigned m2 = __ballot_sync(0xffffffffu, nc > 2);
                unsigned m3 = __ballot_sync(0xffffffffu, nc > 3);
                int excl = __popc(m0 & lt) + __popc(m1 & lt) + __popc(m2 & lt) + __popc(m3 & lt);
                int base = curEnd + total + excl;
                if (q < curEnd) {
                    for (int i = 0; i < nc; i++) { ord[base+i] = ch[i]; pp[base+i] = q; }
                    g_cs[s*NN + q] = (nc << 14) | base;
                }
                total += __popc(m0) + __popc(m1) + __popc(m2) + __popc(m3);
            }
            __syncwarp();
            if (total == 0) break;
            lvl++;
            if (lane == 0) loff[lvl+1] = curEnd + total;
            cur = curEnd; curEnd += total;
        }
        if (lane == 0) g_nlev[s] = lvl + 1;
    }
    __syncthreads();
    float sig = (s & 1) ? 1.0f : 0.02f;
    for (int k = threadIdx.x; k < NN; k += blockDim.x) {
        g_ord[s*NN + k] = ord[k];
        g_pp[s*NN + k]  = pp[k];
        if (k == 0) { g_w[s*NN] = 0.0f; continue; }
        int v = ord[k];
        int u = ord[pp[k]];
        int e;
        if      (u == v-1)  { int r2 = v/WW, c2 = v%WW; e = r2*(WW-1) + (c2-1); }
        else if (u == v+1)  { int r2 = v/WW, c2 = v%WW; e = r2*(WW-1) + c2; }
        else if (u == v-WW) { e = NEH + (v-WW); }
        else                { e = NEH + v; }
        g_w[s*NN + k] = expf(-(float)g_ws[s*NE + e] / sig);
    }
}

// Two-pass tree DP, one block per (batch, channel). Small levels (<=32) run on
// warp 0 with the previous level's values in REGISTERS, parent/child transfer
// via shuffles: no barriers, no atomics on the critical chain. Big levels use
// gather (no atomics) with block barriers. In-place: A -> up result -> S.
__global__ void __launch_bounds__(256) k_filter(int t, int srcsel, int dst) {
    extern __shared__ float shf[];
    float* A = shf;                 // NN (position-indexed; val -> A' -> S)
    float* w = A + NN;              // NN
    int* pp    = (int*)(w + NN);    // NN
    int* csp   = pp + NN;           // NN
    int* loffs = csp + NN;          // NN+4
    int b = blockIdx.x, c = blockIdx.y;
    int s = b*2 + t;
    int nl = g_nlev[s];
    const float* s1c = g_S + (b*(CCH+1) + c)*NN;
    const float* s1n = g_S + (b*(CCH+1) + CCH)*NN;
    const int* ordg = g_ord + s*NN;
    for (int i = threadIdx.x; i < NN; i += 256) {
        int node = ordg[i];
        float v;
        if (c == CCH)           v = 1.0f;
        else if (srcsel == 0)   v = g_prob[(b*CCH + c)*NN + node];
        else                    v = s1c[node] / s1n[node];
        A[i]   = v;
        w[i]   = g_w[s*NN + i];
        pp[i]  = g_pp[s*NN + i];
        csp[i] = g_cs[s*NN + i];
    }
    for (int i = threadIdx.x; i <= nl; i += 256) loffs[i] = g_loff[s*(NN+4) + i];
    __syncthreads();
    int tid = threadIdx.x, lane = tid & 31;
    // ---- UP: leaves -> root (gather from children) ----
    {
        bool regv = false;
        float Aprev = 0.f; int prevS0 = 0;
        for (int d = nl - 1; d >= 0; --d) {
            int s0 = loffs[d], cnt = loffs[d+1] - s0;
            if (cnt <= 32) {
                if (tid < 32) {
                    bool valid = lane < cnt;
                    int k = s0 + (valid ? lane : 0);
                    int cp = csp[k];
                    int cc = valid ? (cp >> 14) : 0;
                    int cs = cp & 16383;
                    float a = A[k];
                    #pragma unroll
                    for (int i = 0; i < 4; i++) {
                        bool has = (i < cc);
                        int cpos = has ? (cs + i) : s0;
                        float wc = w[cpos];
                        float Ac;
                        if (regv) {
                            int sl2 = (cpos - prevS0) & 31;
                            Ac = __shfl_sync(0xffffffffu, Aprev, sl2);
                        } else {
                            Ac = A[cpos];
                        }
                        if (has) a = __fmaf_rn(wc, Ac, a);
                    }
                    if (valid) A[k] = a;
                    Aprev = a;
                }
                prevS0 = s0;
                regv = true;
            } else {
                __syncthreads();
                for (int k = s0 + tid; k < s0 + cnt; k += 256) {
                    int cp = csp[k];
                    int cc = cp >> 14, cs = cp & 16383;
                    float a = A[k];
                    for (int i = 0; i < cc; i++) a = __fmaf_rn(w[cs+i], A[cs+i], a);
                    A[k] = a;
                }
                __syncthreads();
                regv = false;
            }
        }
    }
    __syncthreads();
    // ---- DOWN: root -> leaves (parent via shuffle), in-place A -> S ----
    {
        bool regv = true;
        float Sprev = 0.f; int prevS0 = 0;
        if (tid < 32) Sprev = A[0];   // root S = A' (lane pk-prevS0 = 0 sources lane 0 correctly... all lanes hold A[0])
        for (int d = 1; d < nl; ++d) {
            int s0 = loffs[d], cnt = loffs[d+1] - s0;
            if (cnt <= 32) {
                if (tid < 32) {
                    bool valid = lane < cnt;
                    int k = s0 + (valid ? lane : 0);
                    int pk = pp[k];
                    float a = A[k], wv = w[k];
                    float Sp;
                    if (regv) {
                        int sl2 = (pk - prevS0) & 31;
                        Sp = __shfl_sync(0xffffffffu, Sprev, sl2);
                    } else {
                        Sp = A[pk];
                    }
                    float Sv = __fmaf_rn(wv, __fmaf_rn(-wv, a, Sp), a);
                    if (valid) A[k] = Sv;
                    Sprev = Sv;
                }
                prevS0 = s0;
                regv = true;
            } else {
                __syncthreads();
                for (int k = s0 + tid; k < s0 + cnt; k += 256) {
                    float a = A[k], wv = w[k];
                    A[k] = __fmaf_rn(wv, __fmaf_rn(-wv, a, A[pp[k]]), a);
                }
                __syncthreads();
                regv = false;
            }
        }
    }
    __syncthreads();
    float* outS = ((dst == 0) ? g_S : g_S2) + (b*(CCH+1) + c)*NN;
    for (int i = tid; i < NN; i += 256) outS[ordg[i]] = A[i];
}

__global__ void k_loss(const float* __restrict__ roi) {
    __shared__ double sl[256], sn[256];
    int idx = blockIdx.x*blockDim.x + threadIdx.x;
    double l = 0.0, n = 0.0;
    if (idx < BN*NN) {
        int b = idx / NN, i = idx - b*NN;
        int h = i / WW, w = i - h*WW;
        float r = roi[b*(2*HH)*(2*WW) + (2*h)*(2*WW) + 2*w];
        n = (double)r;
        if (r != 0.0f) {
            float nrm = g_S2[(b*(CCH+1) + CCH)*NN + i];
            double acc = 0.0;
            for (int c = 0; c < CCH; c++) {
                float as = g_S2[(b*(CCH+1) + c)*NN + i] / nrm;
                acc += (double)fabsf(g_prob[(b*CCH + c)*NN + i] - as);
            }
            l = acc * (double)r;
        }
    }
    sl[threadIdx.x] = l; sn[threadIdx.x] = n;
    __syncthreads();
    for (int o = 128; o; o >>= 1) {
        if (threadIdx.x < o) { sl[threadIdx.x] += sl[threadIdx.x+o]; sn[threadIdx.x] += sn[threadIdx.x+o]; }
        __syncthreads();
    }
    if (threadIdx.x == 0) { atomicAdd(&g_acc[0], sl[0]); atomicAdd(&g_acc[1], sn[0]); }
}

__global__ void k_fin(float* out) {
    if (threadIdx.x == 0)
        out[0] = (g_acc[1] > 0.0) ? (float)(g_acc[0]/g_acc[1]) : 0.0f;
}

// ---------------- launch ----------------
extern "C" void kernel_launch(void* const* d_in, const int* in_sizes, int n_in,
                              void* d_out, int out_size) {
    const float* preds = (const float*)d_in[0];
    const float* lf    = (const float*)d_in[1];
    const float* hf    = (const float*)d_in[2];
    const float* roi   = (const float*)d_in[3];
    float* out = (float*)d_out;

    const int smem_boruvka = NN*8 + 3*NN*4;          // 184320
    const int smem_bfs     = 6*NN*4;                 // 221184
    const int smem_filter  = 4*NN*4 + (NN+4)*4;      // 184336
    cudaFuncSetAttribute(k_boruvka, cudaFuncAttributeMaxDynamicSharedMemorySize, smem_boruvka);
    cudaFuncSetAttribute(k_bfs,     cudaFuncAttributeMaxDynamicSharedMemorySize, smem_bfs);
    cudaFuncSetAttribute(k_filter,  cudaFuncAttributeMaxDynamicSharedMemorySize, smem_filter);

    k_sigmoid<<<(BN*CCH*NN + 255)/256, 256>>>(preds);
    k_ew_high<<<(BN*NCHUNK*NE + 255)/256, 256>>>(hf);
    k_ew_red <<<(BN*NE + 255)/256, 256>>>(lf);
    k_boruvka<<<NTREE, 1024, smem_boruvka>>>();
    k_bfs    <<<NTREE, 256, smem_bfs>>>();
    {
        dim3 g1(BN, CCH+1);
        k_filter<<<g1, 256, smem_filter>>>(0, 0, 0);
        k_filter<<<g1, 256, smem_filter>>>(1, 1, 1);
    }
    k_loss   <<<(BN*NN + 255)/256, 256>>>(roi);
    k_fin    <<<1, 32>>>(out);
}